// round 9
// baseline (speedup 1.0000x reference)
#include <cuda_runtime.h>
#include <float.h>

#define V    23
#define Hdim 256
#define Lseq 1024
#define TPB  128   // 4 warps; TWO chains (batch elements) per CTA

// ---- Blackwell packed fp32x2 FMA (PTX-only; doubles fp32 throughput) ----
__device__ __forceinline__ unsigned long long ffma2(unsigned long long a,
                                                    unsigned long long b,
                                                    unsigned long long c) {
    unsigned long long d;
    asm("fma.rn.f32x2 %0, %1, %2, %3;" : "=l"(d) : "l"(a), "l"(b), "l"(c));
    return d;
}
__device__ __forceinline__ unsigned long long pack2(float x, float y) {
    unsigned long long d;
    asm("mov.b64 %0, {%1, %2};" : "=l"(d) : "f"(x), "f"(y));
    return d;
}
__device__ __forceinline__ float2 unpack2(unsigned long long a) {
    float2 r;
    asm("mov.b64 {%0, %1}, %2;" : "=f"(r.x), "=f"(r.y) : "l"(a));
    return r;
}

// Monotonic float->uint key: preserves float ordering (for integer redux max)
__device__ __forceinline__ unsigned fkey(float f) {
    unsigned u = __float_as_uint(f);
    return (u & 0x80000000u) ? ~u : (u | 0x80000000u);
}

// Merge-reduce: fold value `hi` into `lo`, splitting ownership by lane bit.
#define MRG(lo, hi, bit) do {                                   \
    float _keep = (lane & (bit)) ? (hi) : (lo);                 \
    float _send = (lane & (bit)) ? (lo) : (hi);                 \
    (lo) = _keep + __shfl_xor_sync(0xffffffffu, _send, (bit));  \
} while (0)

// Full 12-value merge tree: r0..r11 -> r0 holds per-lane output o_loc
#define TREE12(r0,r1,r2,r3,r4,r5,r6,r7,r8,r9,r10,r11) do {      \
    MRG(r0, r6, 16); MRG(r1, r7, 16); MRG(r2, r8, 16);          \
    MRG(r3, r9, 16); MRG(r4, r10, 16); MRG(r5, r11, 16);        \
    MRG(r0, r3, 8);  MRG(r1, r4, 8);  MRG(r2, r5, 8);           \
    MRG(r0, r1, 4);  r2 += __shfl_xor_sync(0xffffffffu, r2, 4); \
    MRG(r0, r2, 2);                                             \
    r0 += __shfl_xor_sync(0xffffffffu, r0, 1);                  \
} while (0)

__global__ __launch_bounds__(TPB, 2)
void daf_kernel(const int* __restrict__ x_tokens,
                const float* __restrict__ W1,
                const float* __restrict__ b1,
                const float* __restrict__ W2,
                const float* __restrict__ b2,
                float* __restrict__ out)
{
    __shared__ __align__(16) float sW1[V * Hdim]; // 23552 B, row y contiguous
    __shared__ float snet[2][2][48];              // [buf][chain][logit]
    __shared__ int   stok[2][Lseq];               // both chains' tokens
    __shared__ unsigned char smul[V * V];         // (inv(s)*m) % V lookup

    const int tid  = threadIdx.x;
    const int lane = tid & 31;
    const int warp = tid >> 5;
    const int bA   = blockIdx.x * 2;
    const int bB   = bA + 1;

    // ---- one-time setup ----
    for (int i = tid; i < V * Hdim; i += TPB) sW1[i] = W1[i];
    {
        const int* rowA = x_tokens + (size_t)bA * Lseq;
        const int* rowB = x_tokens + (size_t)bB * Lseq;
        for (int i = tid; i < Lseq; i += TPB) { stok[0][i] = rowA[i]; stok[1][i] = rowB[i]; }
    }
    for (int i = tid; i < V * V; i += TPB) {
        int s = i / V, m = i % V;
        int inv = 0;
        if (s) {
            for (int k = 1; k < V; ++k) if ((s * k) % V == 1) inv = k;
        }
        smul[i] = (unsigned char)((inv * m) % V);
    }

    // Per-lane h-row ownership: j_m = (m<4) ? 4*lane+m : 128 + 4*lane + (m-4)
    int jidx[8];
    #pragma unroll
    for (int m = 0; m < 8; ++m)
        jidx[m] = (m < 4) ? (4 * lane + m) : (124 + 4 * lane + m);

    // W2 resident in registers (shared across both chains).
    // warp w owns outputs o = w*12 .. w*12+11 (o<46 valid).
    unsigned long long w2p[6][8];
    #pragma unroll
    for (int p = 0; p < 6; ++p) {
        int o = warp * 12 + 2 * p;
        #pragma unroll
        for (int m = 0; m < 8; ++m) {
            if (o + 1 < 2 * V) {
                float2 t = *reinterpret_cast<const float2*>(W2 + jidx[m] * (2 * V) + o);
                w2p[p][m] = pack2(t.x, t.y);
            } else {
                w2p[p][m] = 0ull;
            }
        }
    }

    // bias in lane registers (added at argmax-read time)
    float rb2a = (lane < V) ? b2[lane]     : 0.0f;
    float rb2b = (lane < V) ? b2[V + lane] : 0.0f;

    // hpre per chain, replicated per warp, in registers. acc0 = 0 -> hpre = b1.
    float hpA[8], hpB[8];
    #pragma unroll
    for (int m = 0; m < 8; ++m) { hpA[m] = b1[jidx[m]]; hpB[m] = hpA[m]; }

    // final-lane -> local output index mapping for the merge reduction
    const int b1b = (lane >> 1) & 1, b2b = (lane >> 2) & 1;
    const int b3b = (lane >> 3) & 1, b4b = (lane >> 4) & 1;
    const int o_loc = warp * 12 + (b1b ? (2 + 3 * b3b + 6 * b4b)
                                       : (b2b + 3 * b3b + 6 * b4b));

    float* opA = out + (size_t)bA * Lseq * V;
    float* opB = out + (size_t)bB * Lseq * V;

    __syncthreads();

    for (int t = 0; t < Lseq; ++t) {
        // 1) both matvecs: independent FMA chains interleave (in-warp ILP)
        unsigned long long aA0=0,aA1=0,aA2=0,aA3=0,aA4=0,aA5=0;
        unsigned long long aB0=0,aB1=0,aB2=0,aB3=0,aB4=0,aB5=0;
        #pragma unroll
        for (int m = 0; m < 8; ++m) {
            float hvA = fmaxf(hpA[m], 0.0f);
            float hvB = fmaxf(hpB[m], 0.0f);
            unsigned long long hA = pack2(hvA, hvA);
            unsigned long long hB = pack2(hvB, hvB);
            aA0 = ffma2(hA, w2p[0][m], aA0);  aB0 = ffma2(hB, w2p[0][m], aB0);
            aA1 = ffma2(hA, w2p[1][m], aA1);  aB1 = ffma2(hB, w2p[1][m], aB1);
            aA2 = ffma2(hA, w2p[2][m], aA2);  aB2 = ffma2(hB, w2p[2][m], aB2);
            aA3 = ffma2(hA, w2p[3][m], aA3);  aB3 = ffma2(hB, w2p[3][m], aB3);
            aA4 = ffma2(hA, w2p[4][m], aA4);  aB4 = ffma2(hB, w2p[4][m], aB4);
            aA5 = ffma2(hA, w2p[5][m], aA5);  aB5 = ffma2(hB, w2p[5][m], aB5);
        }
        float2 qA0 = unpack2(aA0), qA1 = unpack2(aA1), qA2 = unpack2(aA2);
        float2 qA3 = unpack2(aA3), qA4 = unpack2(aA4), qA5 = unpack2(aA5);
        float2 qB0 = unpack2(aB0), qB1 = unpack2(aB1), qB2 = unpack2(aB2);
        float2 qB3 = unpack2(aB3), qB4 = unpack2(aB4), qB5 = unpack2(aB5);

        // 2) two merge trees (13 shfl each); independent -> they overlap
        float rA0=qA0.x,rA1=qA0.y,rA2=qA1.x,rA3=qA1.y,rA4=qA2.x,rA5=qA2.y;
        float rA6=qA3.x,rA7=qA3.y,rA8=qA4.x,rA9=qA4.y,rA10=qA5.x,rA11=qA5.y;
        float rB0=qB0.x,rB1=qB0.y,rB2=qB1.x,rB3=qB1.y,rB4=qB2.x,rB5=qB2.y;
        float rB6=qB3.x,rB7=qB3.y,rB8=qB4.x,rB9=qB4.y,rB10=qB5.x,rB11=qB5.y;
        TREE12(rA0,rA1,rA2,rA3,rA4,rA5,rA6,rA7,rA8,rA9,rA10,rA11);
        TREE12(rB0,rB1,rB2,rB3,rB4,rB5,rB6,rB7,rB8,rB9,rB10,rB11);

        float* snA = snet[t & 1][0];
        float* snB = snet[t & 1][1];
        snA[o_loc] = rA0;          // duplicate lanes write identical values
        snB[o_loc] = rB0;
        __syncthreads();           // the ONLY barrier per step (serves both chains)

        // 3) argmaxes for both chains, redundantly in every warp
        float vA1 = (lane < V) ? snA[lane]     + rb2a : -FLT_MAX;
        float vA2 = (lane < V) ? snA[V + lane] + rb2b : -FLT_MAX;
        float vB1 = (lane < V) ? snB[lane]     + rb2a : -FLT_MAX;
        float vB2 = (lane < V) ? snB[V + lane] + rb2b : -FLT_MAX;
        unsigned kA1 = fkey(vA1), kA2 = fkey(vA2);
        unsigned kB1 = fkey(vB1), kB2 = fkey(vB2);
        unsigned mA1 = __reduce_max_sync(0xffffffffu, kA1);
        unsigned mA2 = __reduce_max_sync(0xffffffffu, kA2);
        unsigned mB1 = __reduce_max_sync(0xffffffffu, kB1);
        unsigned mB2 = __reduce_max_sync(0xffffffffu, kB2);
        int locA = __ffs(__ballot_sync(0xffffffffu, kA1 == mA1)) - 1;
        int scA  = __ffs(__ballot_sync(0xffffffffu, kA2 == mA2)) - 1;
        int locB = __ffs(__ballot_sync(0xffffffffu, kB1 == mB1)) - 1;
        int scB  = __ffs(__ballot_sync(0xffffffffu, kB2 == mB2)) - 1;

        // 4) token arithmetic
        int mdA = stok[0][t] - locA;  mdA += (mdA >> 31) & V;
        int mdB = stok[1][t] - locB;  mdB += (mdB >> 31) & V;
        int yA = smul[scA * V + mdA];
        int yB = smul[scB * V + mdB];

        // 5) one-hot output rows (different warps -> parallel stores)
        if (warp == 3 && lane < V) opA[lane] = (lane == yA) ? 1.0f : 0.0f;
        if (warp == 2 && lane < V) opB[lane] = (lane == yB) ? 1.0f : 0.0f;
        opA += V; opB += V;

        // 6) state updates: hpre += W1[y, :]
        const float4 wAa = *reinterpret_cast<const float4*>(&sW1[yA * Hdim + 4 * lane]);
        const float4 wAb = *reinterpret_cast<const float4*>(&sW1[yA * Hdim + 128 + 4 * lane]);
        const float4 wBa = *reinterpret_cast<const float4*>(&sW1[yB * Hdim + 4 * lane]);
        const float4 wBb = *reinterpret_cast<const float4*>(&sW1[yB * Hdim + 128 + 4 * lane]);
        hpA[0] += wAa.x; hpA[1] += wAa.y; hpA[2] += wAa.z; hpA[3] += wAa.w;
        hpA[4] += wAb.x; hpA[5] += wAb.y; hpA[6] += wAb.z; hpA[7] += wAb.w;
        hpB[0] += wBa.x; hpB[1] += wBa.y; hpB[2] += wBa.z; hpB[3] += wBa.w;
        hpB[4] += wBb.x; hpB[5] += wBb.y; hpB[6] += wBb.z; hpB[7] += wBb.w;
    }
}

extern "C" void kernel_launch(void* const* d_in, const int* in_sizes, int n_in,
                              void* d_out, int out_size) {
    const int*   x  = (const int*)d_in[0];
    const float* W1 = (const float*)d_in[1];
    const float* b1 = (const float*)d_in[2];
    const float* W2 = (const float*)d_in[3];
    const float* b2 = (const float*)d_in[4];
    int Bn = in_sizes[0] / Lseq;   // 512
    daf_kernel<<<Bn / 2, TPB>>>(x, W1, b1, W2, b2, (float*)d_out);
}

// round 10
// speedup vs baseline: 1.1578x; 1.1578x over previous
#include <cuda_runtime.h>
#include <float.h>

#define V    23
#define Hdim 256
#define Lseq 1024
#define TPB  128   // 4 warps, one chain (batch element) per CTA

// ---- Blackwell packed fp32x2 FMA (PTX-only; doubles fp32 throughput) ----
__device__ __forceinline__ unsigned long long ffma2(unsigned long long a,
                                                    unsigned long long b,
                                                    unsigned long long c) {
    unsigned long long d;
    asm("fma.rn.f32x2 %0, %1, %2, %3;" : "=l"(d) : "l"(a), "l"(b), "l"(c));
    return d;
}
__device__ __forceinline__ unsigned long long pack2(float x, float y) {
    unsigned long long d;
    asm("mov.b64 %0, {%1, %2};" : "=l"(d) : "f"(x), "f"(y));
    return d;
}
__device__ __forceinline__ float2 unpack2(unsigned long long a) {
    float2 r;
    asm("mov.b64 {%0, %1}, %2;" : "=f"(r.x), "=f"(r.y) : "l"(a));
    return r;
}

// Monotonic float->uint key, branchless: preserves float ordering
__device__ __forceinline__ unsigned fkey(float f) {
    unsigned u = __float_as_uint(f);
    return u ^ ((unsigned)(((int)u) >> 31) | 0x80000000u);
}

// Merge-reduce with selects (only needed for the final mask-4/mask-2 rounds)
#define MRG(lo, hi, bit) do {                                   \
    float _keep = (lane & (bit)) ? (hi) : (lo);                 \
    float _send = (lane & (bit)) ? (lo) : (hi);                 \
    (lo) = _keep + __shfl_xor_sync(0xffffffffu, _send, (bit));  \
} while (0)

__global__ __launch_bounds__(TPB, 4)
void daf_kernel(const int* __restrict__ x_tokens,
                const float* __restrict__ W1,
                const float* __restrict__ b1,
                const float* __restrict__ W2,
                const float* __restrict__ b2,
                float* __restrict__ out)
{
    __shared__ __align__(16) float sW1[V * Hdim]; // 23552 B, row y contiguous
    __shared__ float snet[2][48];                 // double-buffered logits
    __shared__ int   stok[Lseq];                  // this chain's input tokens
    __shared__ unsigned char smul[V * V];         // (inv(s)*m) % V lookup

    const int tid  = threadIdx.x;
    const int b    = blockIdx.x;
    const int lane = tid & 31;
    const int warp = tid >> 5;

    // ---- one-time setup ----
    for (int i = tid; i < V * Hdim; i += TPB) sW1[i] = W1[i];
    {
        const int* tokrow = x_tokens + (size_t)b * Lseq;
        for (int i = tid; i < Lseq; i += TPB) stok[i] = tokrow[i];
    }
    for (int i = tid; i < V * V; i += TPB) {
        int s = i / V, m = i % V;
        int inv = 0;
        if (s) {
            for (int k = 1; k < V; ++k) if ((s * k) % V == 1) inv = k;
        }
        smul[i] = (unsigned char)((inv * m) % V);
    }

    // Per-lane h-row ownership: j_m = (m<4) ? 4*lane+m : 128 + 4*lane + (m-4)
    int jidx[8];
    #pragma unroll
    for (int m = 0; m < 8; ++m)
        jidx[m] = (m < 4) ? (4 * lane + m) : (124 + 4 * lane + m);

    // W2 resident in registers, packed as f32x2 pairs, with the SELECT-FREE
    // TREE PERMUTATION baked in: scalar accumulator k (k=6a+3b+c) on this
    // lane holds logical output q(k) = 6*(a^b4) + 3*(b^b3) + c, where
    // b3/b4 are lane bits 3/4. This makes the mask-16 and mask-8 reduction
    // rounds plain add+shuffle (no selects); register contents at the mask-4
    // boundary are identical to the original select-based tree.
    const int lb3 = (lane >> 3) & 1;
    const int lb4 = (lane >> 4) & 1;
    unsigned long long w2p[6][8];
    #pragma unroll
    for (int p = 0; p < 6; ++p) {
        int k0 = 2 * p, k1 = 2 * p + 1;
        int q0 = 6 * ((k0 / 6) ^ lb4) + 3 * (((k0 % 6) / 3) ^ lb3) + (k0 % 3);
        int q1 = 6 * ((k1 / 6) ^ lb4) + 3 * (((k1 % 6) / 3) ^ lb3) + (k1 % 3);
        int o0 = warp * 12 + q0;
        int o1 = warp * 12 + q1;
        #pragma unroll
        for (int m = 0; m < 8; ++m) {
            const float* row = W2 + jidx[m] * (2 * V);
            float v0 = (o0 < 2 * V) ? row[o0] : 0.0f;
            float v1 = (o1 < 2 * V) ? row[o1] : 0.0f;
            w2p[p][m] = pack2(v0, v1);
        }
    }

    // bias in lane registers (added at argmax-read time)
    float rb2a = (lane < V) ? b2[lane]     : 0.0f;
    float rb2b = (lane < V) ? b2[V + lane] : 0.0f;

    // hpre replicated per warp, in registers. acc0 = 0 -> hpre = b1.
    float hp8[8];
    #pragma unroll
    for (int m = 0; m < 8; ++m) hp8[m] = b1[jidx[m]];

    // final-lane -> local output index mapping (unchanged: contents at the
    // mask-4 boundary match the original tree)
    const int b1b = (lane >> 1) & 1, b2b = (lane >> 2) & 1;
    const int b3b = (lane >> 3) & 1, b4b = (lane >> 4) & 1;
    const int o_loc = warp * 12 + (b1b ? (2 + 3 * b3b + 6 * b4b)
                                       : (b2b + 3 * b3b + 6 * b4b));

    float* op = out + (size_t)b * Lseq * V;

    __syncthreads();

    for (int t = 0; t < Lseq; ++t) {
        // 1) matvec: each warp has ALL of h in registers (relu on the fly)
        unsigned long long a0 = 0, a1 = 0, a2 = 0, a3 = 0, a4 = 0, a5 = 0;
        #pragma unroll
        for (int m = 0; m < 8; ++m) {
            float hv = fmaxf(hp8[m], 0.0f);
            unsigned long long hp = pack2(hv, hv);
            a0 = ffma2(hp, w2p[0][m], a0);
            a1 = ffma2(hp, w2p[1][m], a1);
            a2 = ffma2(hp, w2p[2][m], a2);
            a3 = ffma2(hp, w2p[3][m], a3);
            a4 = ffma2(hp, w2p[4][m], a4);
            a5 = ffma2(hp, w2p[5][m], a5);
        }
        float2 q0 = unpack2(a0), q1 = unpack2(a1), q2 = unpack2(a2);
        float2 q3 = unpack2(a3), q4 = unpack2(a4), q5 = unpack2(a5);
        float r0 = q0.x, r1 = q0.y, r2  = q1.x, r3  = q1.y, r4  = q2.x, r5  = q2.y;
        float r6 = q3.x, r7 = q3.y, r8  = q4.x, r9  = q4.y, r10 = q5.x, r11 = q5.y;

        // 2) reduction tree: mask-16 and mask-8 rounds are SELECT-FREE
        //    (permutation baked into W2 loads); selects only in last rounds.
        r0 += __shfl_xor_sync(0xffffffffu, r6,  16);
        r1 += __shfl_xor_sync(0xffffffffu, r7,  16);
        r2 += __shfl_xor_sync(0xffffffffu, r8,  16);
        r3 += __shfl_xor_sync(0xffffffffu, r9,  16);
        r4 += __shfl_xor_sync(0xffffffffu, r10, 16);
        r5 += __shfl_xor_sync(0xffffffffu, r11, 16);
        r0 += __shfl_xor_sync(0xffffffffu, r3,  8);
        r1 += __shfl_xor_sync(0xffffffffu, r4,  8);
        r2 += __shfl_xor_sync(0xffffffffu, r5,  8);
        MRG(r0, r1, 4);
        r2 += __shfl_xor_sync(0xffffffffu, r2, 4);
        MRG(r0, r2, 2);
        r0 += __shfl_xor_sync(0xffffffffu, r0, 1);

        float* sn = snet[t & 1];
        sn[o_loc] = r0;            // duplicate lanes write identical values
        __syncthreads();           // the ONLY barrier per step

        // 3) both argmaxes, redundantly in every warp (first-index tie-break)
        float v1 = (lane < V) ? sn[lane]     + rb2a : -FLT_MAX;
        float v2 = (lane < V) ? sn[V + lane] + rb2b : -FLT_MAX;
        unsigned k1 = fkey(v1);
        unsigned m1 = __reduce_max_sync(0xffffffffu, k1);
        int loc = __ffs(__ballot_sync(0xffffffffu, k1 == m1)) - 1;
        unsigned k2 = fkey(v2);
        unsigned m2 = __reduce_max_sync(0xffffffffu, k2);
        int sc  = __ffs(__ballot_sync(0xffffffffu, k2 == m2)) - 1;

        // 4) token arithmetic (uniform across CTA)
        int a0t = stok[t];
        int md  = a0t - loc;
        md += (md >> 31) & V;                  // (a0 - loc) mod 23
        int y = smul[sc * V + md];             // (inv(sc) * md) mod 23

        // 5) one-hot output row (warp 3 only; covers whole poisoned buffer)
        if (warp == 3 && lane < V) op[lane] = (lane == y) ? 1.0f : 0.0f;
        op += V;

        // 6) per-warp state update: hpre += W1[y, :]
        const float4 wa = *reinterpret_cast<const float4*>(&sW1[y * Hdim + 4 * lane]);
        const float4 wb = *reinterpret_cast<const float4*>(&sW1[y * Hdim + 128 + 4 * lane]);
        hp8[0] += wa.x; hp8[1] += wa.y; hp8[2] += wa.z; hp8[3] += wa.w;
        hp8[4] += wb.x; hp8[5] += wb.y; hp8[6] += wb.z; hp8[7] += wb.w;
    }
}

extern "C" void kernel_launch(void* const* d_in, const int* in_sizes, int n_in,
                              void* d_out, int out_size) {
    const int*   x  = (const int*)d_in[0];
    const float* W1 = (const float*)d_in[1];
    const float* b1 = (const float*)d_in[2];
    const float* W2 = (const float*)d_in[3];
    const float* b2 = (const float*)d_in[4];
    int Bn = in_sizes[0] / Lseq;   // 512
    daf_kernel<<<Bn, TPB>>>(x, W1, b1, W2, b2, (float*)d_out);
}

// round 14
// speedup vs baseline: 1.2379x; 1.0692x over previous
#include <cuda_runtime.h>
#include <float.h>

#define V    23
#define Hdim 256
#define Lseq 1024
#define TPB  128   // 4 warps, one chain (batch element) per CTA

// ---- Blackwell packed fp32x2 FMA (PTX-only; doubles fp32 throughput) ----
__device__ __forceinline__ unsigned long long ffma2(unsigned long long a,
                                                    unsigned long long b,
                                                    unsigned long long c) {
    unsigned long long d;
    asm("fma.rn.f32x2 %0, %1, %2, %3;" : "=l"(d) : "l"(a), "l"(b), "l"(c));
    return d;
}
__device__ __forceinline__ unsigned long long pack2(float x, float y) {
    unsigned long long d;
    asm("mov.b64 %0, {%1, %2};" : "=l"(d) : "f"(x), "f"(y));
    return d;
}
__device__ __forceinline__ float2 unpack2(unsigned long long a) {
    float2 r;
    asm("mov.b64 {%0, %1}, %2;" : "=f"(r.x), "=f"(r.y) : "l"(a));
    return r;
}

// Monotonic float->uint key, branchless: preserves float ordering
__device__ __forceinline__ unsigned fkey(float f) {
    unsigned u = __float_as_uint(f);
    return u ^ ((unsigned)(((int)u) >> 31) | 0x80000000u);
}

// Merge-reduce with selects (only the final mask-4/mask-2 rounds need them)
#define MRG(lo, hi, bit) do {                                   \
    float _keep = (lane & (bit)) ? (hi) : (lo);                 \
    float _send = (lane & (bit)) ? (lo) : (hi);                 \
    (lo) = _keep + __shfl_xor_sync(0xffffffffu, _send, (bit));  \
} while (0)

// mod-inverse table mod 23, 5 bits per entry, in two u64 constants
// s = 0..11 -> INV_LO, s = 12..22 -> INV_HI
#define INV_LO ( 0ull | (1ull<<5) | (12ull<<10) | (8ull<<15) | (6ull<<20) | \
                (14ull<<25) | (4ull<<30) | (10ull<<35) | (3ull<<40) |      \
                (18ull<<45) | (7ull<<50) | (21ull<<55) )
#define INV_HI ( 2ull | (16ull<<5) | (5ull<<10) | (20ull<<15) | (13ull<<20) | \
                (19ull<<25) | (9ull<<30) | (17ull<<35) | (15ull<<40) |       \
                (11ull<<45) | (22ull<<50) )

__global__ __launch_bounds__(TPB, 4)
void daf_kernel(const int* __restrict__ x_tokens,
                const float* __restrict__ W1,
                const float* __restrict__ b1,
                const float* __restrict__ W2,
                const float* __restrict__ b2,
                float* __restrict__ out)
{
    __shared__ __align__(16) float sW1[V * Hdim];  // 23552 B, row y contiguous
    __shared__ __align__(16) unsigned pm[2][8];    // [buf][0..3]=keys, [4..7]=idx
    __shared__ int stok[Lseq];                     // this chain's input tokens

    const int tid  = threadIdx.x;
    const int b    = blockIdx.x;
    const int lane = tid & 31;
    const int warp = tid >> 5;

    // Output-group repartition: each warp's 12 logits lie in ONE argmax group.
    // warp0: loc[0..11], warp1: loc[12..22], warp2: sc[0..11], warp3: sc[12..22]
    const int g    = warp >> 1;        // 0 = loc group, 1 = scale group
    const int base = (warp & 1) * 12;  // within-group offset (warps 1,3: 11 valid + 1 pad)

    // ---- one-time setup ----
    for (int i = tid; i < V * Hdim; i += TPB) sW1[i] = W1[i];
    {
        const int* tokrow = x_tokens + (size_t)b * Lseq;
        for (int i = tid; i < Lseq; i += TPB) stok[i] = tokrow[i];
    }

    // Per-lane h-row ownership: j_m = (m<4) ? 4*lane+m : 128 + 4*lane + (m-4)
    int jidx[8];
    #pragma unroll
    for (int m = 0; m < 8; ++m)
        jidx[m] = (m < 4) ? (4 * lane + m) : (124 + 4 * lane + m);

    // W2 in registers with the select-free tree permutation baked in:
    // scalar accumulator k (k=6a+3b+c) on this lane holds logical within-warp
    // output q(k) = 6*(a^b4) + 3*(b^b3) + c  (b3/b4 = lane bits 3/4).
    // W2 column for within-warp output q:  col = g*23 + base + q  (pad -> 0).
    const int lb3 = (lane >> 3) & 1;
    const int lb4 = (lane >> 4) & 1;
    unsigned long long w2p[6][8];
    #pragma unroll
    for (int p = 0; p < 6; ++p) {
        int k0 = 2 * p, k1 = 2 * p + 1;
        int q0 = 6 * ((k0 / 6) ^ lb4) + 3 * (((k0 % 6) / 3) ^ lb3) + (k0 % 3);
        int q1 = 6 * ((k1 / 6) ^ lb4) + 3 * (((k1 % 6) / 3) ^ lb3) + (k1 % 3);
        int i0 = base + q0, i1 = base + q1;        // index within group (0..22 valid)
        int o0 = g * V + i0, o1 = g * V + i1;      // W2 column
        #pragma unroll
        for (int m = 0; m < 8; ++m) {
            const float* row = W2 + jidx[m] * (2 * V);
            float v0 = (i0 < V) ? row[o0] : 0.0f;
            float v1 = (i1 < V) ? row[o1] : 0.0f;
            w2p[p][m] = pack2(v0, v1);
        }
    }

    // after the tree, r0 on this lane holds within-warp output q_loc:
    const int b1b = (lane >> 1) & 1, b2b = (lane >> 2) & 1;
    const int q_loc = b1b ? (2 + 3 * lb3 + 6 * lb4) : (b2b + 3 * lb3 + 6 * lb4);
    const int i_gr  = base + q_loc;               // index within argmax group
    const bool vld  = (i_gr < V);
    const float rbias = vld ? b2[g * V + i_gr] : 0.0f;

    // hpre replicated per warp, in registers. acc0 = 0 -> hpre = b1.
    float hp8[8];
    #pragma unroll
    for (int m = 0; m < 8; ++m) hp8[m] = b1[jidx[m]];

    float* op = out + (size_t)b * Lseq * V;

    __syncthreads();

    for (int t = 0; t < Lseq; ++t) {
        // 1) matvec: each warp has ALL of h in registers (relu on the fly)
        unsigned long long a0 = 0, a1 = 0, a2 = 0, a3 = 0, a4 = 0, a5 = 0;
        #pragma unroll
        for (int m = 0; m < 8; ++m) {
            float hv = fmaxf(hp8[m], 0.0f);
            unsigned long long hp = pack2(hv, hv);
            a0 = ffma2(hp, w2p[0][m], a0);
            a1 = ffma2(hp, w2p[1][m], a1);
            a2 = ffma2(hp, w2p[2][m], a2);
            a3 = ffma2(hp, w2p[3][m], a3);
            a4 = ffma2(hp, w2p[4][m], a4);
            a5 = ffma2(hp, w2p[5][m], a5);
        }
        float2 q0 = unpack2(a0), q1 = unpack2(a1), q2 = unpack2(a2);
        float2 q3 = unpack2(a3), q4 = unpack2(a4), q5 = unpack2(a5);
        float r0 = q0.x, r1 = q0.y, r2  = q1.x, r3  = q1.y, r4  = q2.x, r5  = q2.y;
        float r6 = q3.x, r7 = q3.y, r8  = q4.x, r9  = q4.y, r10 = q5.x, r11 = q5.y;

        // 2) reduction tree (mask-16/8 select-free via permuted W2 loads)
        r0 += __shfl_xor_sync(0xffffffffu, r6,  16);
        r1 += __shfl_xor_sync(0xffffffffu, r7,  16);
        r2 += __shfl_xor_sync(0xffffffffu, r8,  16);
        r3 += __shfl_xor_sync(0xffffffffu, r9,  16);
        r4 += __shfl_xor_sync(0xffffffffu, r10, 16);
        r5 += __shfl_xor_sync(0xffffffffu, r11, 16);
        r0 += __shfl_xor_sync(0xffffffffu, r3,  8);
        r1 += __shfl_xor_sync(0xffffffffu, r4,  8);
        r2 += __shfl_xor_sync(0xffffffffu, r5,  8);
        MRG(r0, r1, 4);
        r2 += __shfl_xor_sync(0xffffffffu, r2, 4);
        MRG(r0, r2, 2);
        r0 += __shfl_xor_sync(0xffffffffu, r0, 1);

        // 3) PRE-BAR argmax, EXACT: full-precision key redux-max, then
        //    redux-min over group indices of the max-achieving lanes
        //    (exact first-index tie-break, matches jnp.argmax).
        unsigned key  = vld ? fkey(r0 + rbias) : 0u;
        unsigned km   = __reduce_max_sync(0xffffffffu, key);
        unsigned cand = (key == km && vld) ? (unsigned)i_gr : 1023u;
        unsigned imin = __reduce_min_sync(0xffffffffu, cand);
        if (lane == 0) { pm[t & 1][warp] = km; pm[t & 1][4 + warp] = imin; }
        __syncthreads();           // the ONLY barrier per step

        // 4) post-bar: combine 4 warp (key,idx) pairs -> loc, sc.
        //    warp0/2 hold smaller indices, so '>=' keeps first-index ties.
        const uint4 pk = *reinterpret_cast<const uint4*>(&pm[t & 1][0]);
        const uint4 pi = *reinterpret_cast<const uint4*>(&pm[t & 1][4]);
        int loc = (pk.x >= pk.y) ? (int)pi.x : (int)pi.y;
        int sc  = (pk.z >= pk.w) ? (int)pi.z : (int)pi.w;

        // 5) token arithmetic, ALU-only (no table lookups)
        int md = stok[t] - loc;
        md += (md >> 31) & V;                       // (a0 - loc) mod 23
        unsigned inv = (unsigned)(((sc < 12) ? (INV_LO >> (5 * sc))
                                             : (INV_HI >> (5 * (sc - 12)))) & 31ull);
        int mprod = (int)inv * md;                  // <= 22*22 = 484
        int y = mprod - V * ((mprod * 5699) >> 17); // exact (inv*md) % 23

        // 6) one-hot output row (warp 3 only; covers whole poisoned buffer)
        if (warp == 3 && lane < V) op[lane] = (lane == y) ? 1.0f : 0.0f;
        op += V;

        // 7) per-warp state update: hpre += W1[y, :]
        const float4 wa = *reinterpret_cast<const float4*>(&sW1[y * Hdim + 4 * lane]);
        const float4 wb = *reinterpret_cast<const float4*>(&sW1[y * Hdim + 128 + 4 * lane]);
        hp8[0] += wa.x; hp8[1] += wa.y; hp8[2] += wa.z; hp8[3] += wa.w;
        hp8[4] += wb.x; hp8[5] += wb.y; hp8[6] += wb.z; hp8[7] += wb.w;
    }
}

extern "C" void kernel_launch(void* const* d_in, const int* in_sizes, int n_in,
                              void* d_out, int out_size) {
    const int*   x  = (const int*)d_in[0];
    const float* W1 = (const float*)d_in[1];
    const float* b1 = (const float*)d_in[2];
    const float* W2 = (const float*)d_in[3];
    const float* b2 = (const float*)d_in[4];
    int Bn = in_sizes[0] / Lseq;   // 512
    daf_kernel<<<Bn, TPB>>>(x, W1, b1, W2, b2, (float*)d_out);
}